// round 13
// baseline (speedup 1.0000x reference)
#include <cuda_runtime.h>
#include <cuda_bf16.h>
#include <cstdint>
#include <math.h>

// Problem constants
#define BB   4
#define SS   1024
#define EMB  128
#define HH   4
#define DD   32
#define NTOK (BB*SS)          // 4096
#define NQ   (BB*(SS-1))      // 4092
#define SCALE 0.17677669529663687f  // 1/sqrt(32)
#define TOK  8                // tokens per block (prep / mlp)
#define ACHK 8                // attention staging chunk rows
#define AQ   32               // attention queries per tile
#define NSP  8                // attention splits (warps) per block

typedef unsigned long long u64t;
typedef unsigned int       u32t;

// ---------------- packed f32x2 helpers (SASS FFMA2 path) ---------------------
__device__ __forceinline__ u64t pk2(float lo, float hi){
    u64t r; asm("mov.b64 %0,{%1,%2};":"=l"(r):"f"(lo),"f"(hi)); return r;
}
__device__ __forceinline__ void fma2(u64t& d, u64t a, u64t b){
    asm("fma.rn.f32x2 %0,%1,%2,%0;":"+l"(d):"l"(a),"l"(b));
}
__device__ __forceinline__ u64t add2(u64t a, u64t b){
    u64t r; asm("add.rn.f32x2 %0,%1,%2;":"=l"(r):"l"(a),"l"(b)); return r;
}
__device__ __forceinline__ void unpk2(u64t v, float& lo, float& hi){
    asm("mov.b64 {%0,%1},%2;":"=f"(lo),"=f"(hi):"l"(v));
}
__device__ __forceinline__ float hadd2(u64t v){
    float lo, hi; unpk2(v, lo, hi); return lo + hi;
}

// ---------------- cp.async helpers ------------------------------------------
__device__ __forceinline__ void cpa16(u32t s, const void* g){
    asm volatile("cp.async.ca.shared.global [%0], [%1], 16;" :: "r"(s), "l"(g));
}
__device__ __forceinline__ void cpa4(u32t s, const void* g){
    asm volatile("cp.async.ca.shared.global [%0], [%1], 4;" :: "r"(s), "l"(g));
}
__device__ __forceinline__ void cpa_commit(){
    asm volatile("cp.async.commit_group;");
}
__device__ __forceinline__ void cpa_wait1(){
    asm volatile("cp.async.wait_group 1;");
}
__device__ __forceinline__ void cpa_wait0(){
    asm volatile("cp.async.wait_group 0;");
}

// ---------------- scratch (static device globals; no allocation) -------------
__device__ float g_e  [NTOK*EMB];
__device__ float g_Q  [NTOK*EMB];
__device__ float g_K  [NTOK*EMB];
__device__ float g_V  [NTOK*EMB];
__device__ float g_sr [HH*BB*SS];     // raw Q.K dot per (h,b,s), unscaled
__device__ float g_ctx[NQ*EMB];
__device__ float g_Ep [BB*(SS+1)*HH];
__device__ float g_Pp [BB*(SS+1)];
__device__ float g_theta[HH];

// =====================================================================
// Kernel 1: gather e,a; Q=eWq+bq, K=eWk+bk, inter=[e,a]Wh+bh, V=inter Wv+bv
// + per-token Q.K head dots (quarter-0: warp w == head w).
// 8 tokens/block (512 blocks), 512 threads = (col j, k-quarter).
// =====================================================================
__device__ __forceinline__ void pass_acc(const float (*src)[EMB],
                                         const float* __restrict__ Wr0,
                                         int j, int ks0, int cnt, u64t* accp)
{
    #pragma unroll 4
    for (int kk = 0; kk < cnt; kk += 4) {
        float w0 = Wr0[(kk+0)*EMB + j], w1 = Wr0[(kk+1)*EMB + j];
        float w2 = Wr0[(kk+2)*EMB + j], w3 = Wr0[(kk+3)*EMB + j];
        u64t wA = pk2(w0, w1), wB = pk2(w2, w3);
        #pragma unroll
        for (int t = 0; t < TOK; t++) {
            ulonglong2 f = *(const ulonglong2*)&src[t][ks0 + kk];
            fma2(accp[t], f.x, wA);
            fma2(accp[t], f.y, wB);
        }
    }
}

__global__ void __launch_bounds__(512) prep_kernel(
    const int* __restrict__ idxs, const int* __restrict__ flags,
    const float* __restrict__ item_emb, const float* __restrict__ ans_emb,
    const float* __restrict__ Wq, const float* __restrict__ bq,
    const float* __restrict__ Wk, const float* __restrict__ bk,
    const float* __restrict__ Wv, const float* __restrict__ bv,
    const float* __restrict__ Wh, const float* __restrict__ bh)
{
    __shared__ float e_sh[TOK][EMB];
    __shared__ float a_sh[TOK][EMB];
    __shared__ float i_sh[TOK][EMB];
    __shared__ float pbuf[3][TOK][EMB];

    const int tid = threadIdx.x;
    const int j   = tid & 127;
    const int qt  = tid >> 7;            // quarter 0..3
    const int base = blockIdx.x * TOK;

    if (qt == 0) {
        #pragma unroll
        for (int t = 0; t < TOK; t++)
            e_sh[t][j] = item_emb[(long)idxs[base + t] * EMB + j];
    } else if (qt == 1) {
        #pragma unroll
        for (int t = 0; t < TOK; t++)
            a_sh[t][j] = ans_emb[flags[base + t] * EMB + j];
    }
    __syncthreads();
    if (qt == 0) {
        #pragma unroll
        for (int t = 0; t < TOK; t++)
            g_e[(base + t) * EMB + j] = e_sh[t][j];
    }

    u64t accp[TOK];
    float qv[TOK];                        // final Q values (quarter-0 only)

    // ---- Q ----
    #pragma unroll
    for (int t = 0; t < TOK; t++) accp[t] = 0ull;
    pass_acc(e_sh, Wq + qt*32*EMB, j, qt*32, 32, accp);
    if (qt) {
        #pragma unroll
        for (int t = 0; t < TOK; t++) pbuf[qt-1][t][j] = hadd2(accp[t]);
    }
    __syncthreads();
    if (!qt) {
        float bbv = bq[j];
        #pragma unroll
        for (int t = 0; t < TOK; t++) {
            float v = hadd2(accp[t]) + pbuf[0][t][j] + pbuf[1][t][j] + pbuf[2][t][j] + bbv;
            g_Q[(base+t)*EMB + j] = v;
            qv[t] = v;
        }
    }
    __syncthreads();

    // ---- K (+ fused Q.K head dot) ----
    #pragma unroll
    for (int t = 0; t < TOK; t++) accp[t] = 0ull;
    pass_acc(e_sh, Wk + qt*32*EMB, j, qt*32, 32, accp);
    if (qt) {
        #pragma unroll
        for (int t = 0; t < TOK; t++) pbuf[qt-1][t][j] = hadd2(accp[t]);
    }
    __syncthreads();
    if (!qt) {
        float bbv = bk[j];
        const int w  = j >> 5;            // warp index == head index (quarter 0)
        const int bb = base >> 10;        // batch (tokens of a block share b)
        const int s0 = base & 1023;
        #pragma unroll
        for (int t = 0; t < TOK; t++) {
            float v = hadd2(accp[t]) + pbuf[0][t][j] + pbuf[1][t][j] + pbuf[2][t][j] + bbv;
            g_K[(base+t)*EMB + j] = v;
            float pr = qv[t] * v;
            #pragma unroll
            for (int o = 16; o; o >>= 1) pr += __shfl_xor_sync(0xffffffffu, pr, o);
            if ((j & 31) == 0) g_sr[(w*BB + bb)*SS + s0 + t] = pr;
        }
    }
    __syncthreads();

    // ---- inter = [e,a] @ Wh + bh  (quarters 0,1: e-part; 2,3: a-part) ----
    #pragma unroll
    for (int t = 0; t < TOK; t++) accp[t] = 0ull;
    if (qt < 2) pass_acc(e_sh, Wh + qt*64*EMB,          j, qt*64,     64, accp);
    else        pass_acc(a_sh, Wh + (128 + (qt-2)*64)*EMB, j, (qt-2)*64, 64, accp);
    if (qt) {
        #pragma unroll
        for (int t = 0; t < TOK; t++) pbuf[qt-1][t][j] = hadd2(accp[t]);
    }
    __syncthreads();
    if (!qt) {
        float bbv = bh[j];
        #pragma unroll
        for (int t = 0; t < TOK; t++)
            i_sh[t][j] = hadd2(accp[t]) + pbuf[0][t][j] + pbuf[1][t][j] + pbuf[2][t][j] + bbv;
    }
    __syncthreads();

    // ---- V = inter @ Wv + bv ----
    #pragma unroll
    for (int t = 0; t < TOK; t++) accp[t] = 0ull;
    pass_acc(i_sh, Wv + qt*32*EMB, j, qt*32, 32, accp);
    if (qt) {
        #pragma unroll
        for (int t = 0; t < TOK; t++) pbuf[qt-1][t][j] = hadd2(accp[t]);
    }
    __syncthreads();
    if (!qt) {
        float bbv = bv[j];
        #pragma unroll
        for (int t = 0; t < TOK; t++)
            g_V[(base+t)*EMB + j] = hadd2(accp[t]) + pbuf[0][t][j] + pbuf[1][t][j] + pbuf[2][t][j] + bbv;
    }
}

// =====================================================================
// Kernel 2: scans (slim). grid (BB, HH+1) x 1024 threads.
// =====================================================================
__device__ __forceinline__ float blk_scan(float v, float* sbuf)
{
    const int lane = threadIdx.x & 31, wid = threadIdx.x >> 5;
    #pragma unroll
    for (int o = 1; o < 32; o <<= 1) {
        float n = __shfl_up_sync(0xffffffffu, v, o);
        if (lane >= o) v += n;
    }
    if (lane == 31) sbuf[wid] = v;
    __syncthreads();
    if (wid == 0) {
        float w = sbuf[lane];
        #pragma unroll
        for (int o = 1; o < 32; o <<= 1) {
            float n = __shfl_up_sync(0xffffffffu, w, o);
            if (lane >= o) w += n;
        }
        sbuf[lane] = w;
    }
    __syncthreads();
    float r = v + (wid ? sbuf[wid - 1] : 0.0f);
    __syncthreads();
    return r;
}

__device__ __forceinline__ float blk_max(float v, float* sbuf)
{
    const int lane = threadIdx.x & 31, wid = threadIdx.x >> 5;
    #pragma unroll
    for (int o = 16; o; o >>= 1) v = fmaxf(v, __shfl_xor_sync(0xffffffffu, v, o));
    if (lane == 0) sbuf[wid] = v;
    __syncthreads();
    if (wid == 0) {
        float w = sbuf[lane];
        #pragma unroll
        for (int o = 16; o; o >>= 1) w = fmaxf(w, __shfl_xor_sync(0xffffffffu, w, o));
        if (lane == 0) sbuf[0] = w;
    }
    __syncthreads();
    float r = sbuf[0];
    __syncthreads();
    return r;
}

__global__ void __launch_bounds__(1024) scan_kernel(
    const float* __restrict__ gaps, const float* __restrict__ theta_raw)
{
    __shared__ float sbuf[32];
    const int b = blockIdx.x;
    const int h = blockIdx.y;
    const int s = threadIdx.x;

    if (h == HH) {
        if (b == 0 && s < HH) {
            float x = theta_raw[s];
            float sp = (x > 20.f) ? x : log1pf(expf(x));
            g_theta[s] = sp + 1e-4f;
        }
        float g = fmaxf(gaps[b*SS + s], 1.0f);
        float gi = blk_scan(g, sbuf);
        g_Pp[b*(SS+1) + s + 1] = gi;
        if (s == 0) g_Pp[b*(SS+1)] = 0.f;
        return;
    }

    float sr = g_sr[(h*BB + b)*SS + s] * SCALE;
    float m = blk_max(sr, sbuf);
    float ex = expf(sr - m);
    float ei = blk_scan(ex, sbuf);
    g_Ep[(b*(SS+1) + s + 1)*HH + h] = ei;
    if (s == 0) g_Ep[(b*(SS+1))*HH + h] = 0.f;
}

// =====================================================================
// Kernel 3: causal decayed attention.
// grid (32 qtiles heavy-first, 16 bh); block 256 = 32 queries x 8 splits.
// Each split = ONE WARP with private double-buffered cp.async staging.
// __launch_bounds__(256,3): cap regs ~85 so 3 blocks (24 warps) fit per SM.
// =====================================================================
__global__ void __launch_bounds__(256, 3) attn_kernel()
{
    // smem layout (floats):
    //   Ks : [8 split][2 buf][ACHK*DD]   at 0     (4096)
    //   Vs : same                        at 4096  (4096)
    //   Eps: [8][2][ACHK]                at 8192  (128)
    //   Pps: [8][2][ACHK]                at 8320  (128)
    // combine phase aliases [7][AQ][33] (7392) at offset 0 after full drain.
    __shared__ float SB[8448];

    const int qtile = 31 - (int)blockIdx.x;   // heaviest tile first
    const int bh = blockIdx.y;
    const int b = bh >> 2, h = bh & 3;
    const int tid = threadIdx.x;
    const int ql = tid & 31;
    const int sp = tid >> 5;                  // split (= warp) 0..7

    const int q = 1 + qtile*AQ + ql;          // 1..1024
    const bool active = (q <= SS - 1);
    const int qc = active ? q : (SS - 1);

    const float negtheta = -g_theta[h];

    u64t Qp[16];
    {
        const ulonglong2* qp = (const ulonglong2*)&g_Q[(b*SS + qc)*EMB + h*DD];
        #pragma unroll
        for (int jj = 0; jj < 8; jj++) { ulonglong2 v = qp[jj]; Qp[2*jj] = v.x; Qp[2*jj+1] = v.y; }
    }
    const float Et    = g_Ep[(b*(SS+1) + qc)*HH + h];
    const float Ppq   = g_Pp[b*(SS+1) + qc];
    const float invEt = 1.0f / Et;

    float l = 0.f;
    u64t ctxp[16];
    #pragma unroll
    for (int p = 0; p < 16; p++) ctxp[p] = 0ull;

    const u32t sb0 = (u32t)__cvta_generic_to_shared(SB);
    const int nch = (qtile + 1) * (AQ / ACHK);  // ACHK-row chunks covering keys < qmax

    // issue cp.async loads for chunk `c` into buffer `bf` of this warp-split
    auto load_chunk = [&](int c, int bf) {
        int ib = c * ACHK;
        if (ib > SS - ACHK) ib = SS - ACHK;   // clamp (dummy prefetch)
        u32t sK = sb0 + (u32t)((sp*2 + bf) * (ACHK*DD)) * 4u;
        u32t sV = sK + 4096u * 4u;
        // 64 float4 per array; warp lane ql covers f = ql + {0,32}
        #pragma unroll
        for (int rep = 0; rep < 2; rep++) {
            int f = ql + rep*32;
            int r = f >> 3, d4 = f & 7;
            cpa16(sK + (u32t)f*16u, &g_K[(b*SS + ib + r)*EMB + h*DD + d4*4]);
            cpa16(sV + (u32t)f*16u, &g_V[(b*SS + ib + r)*EMB + h*DD + d4*4]);
        }
        if (ql < ACHK) {
            cpa4(sb0 + (u32t)(8192 + (sp*2 + bf)*ACHK + ql) * 4u,
                 &g_Ep[(b*(SS+1) + ib + ql)*HH + h]);
        } else if (ql < 2*ACHK) {
            int r = ql - ACHK;
            cpa4(sb0 + (u32t)(8320 + (sp*2 + bf)*ACHK + r) * 4u,
                 &g_Pp[b*(SS+1) + ib + r]);
        }
        cpa_commit();
    };

    // prologue: chunk sp -> buffer 0
    load_chunk(sp, 0);

    int buf = 0;
    for (int c = sp; c < nch; c += NSP) {
        load_chunk(c + NSP, buf ^ 1);         // prefetch next
        cpa_wait1();                          // this lane's chunk-c group done
        __syncwarp();                         // all lanes' writes visible

        const int ibase = c * ACHK;
        const float* myK = SB        + (sp*2 + buf)*(ACHK*DD);
        const float* myV = SB + 4096 + (sp*2 + buf)*(ACHK*DD);
        const float* myE = SB + 8192 + (sp*2 + buf)*ACHK;
        const float* myP = SB + 8320 + (sp*2 + buf)*ACHK;

        int iend = q - ibase;
        if (iend > ACHK) iend = ACHK;
        if (!active) iend = 0;

        // ---- phase 1: ACHK independent dot products ----
        float svals[ACHK];
        #pragma unroll
        for (int ii = 0; ii < ACHK; ii++) {
            const ulonglong2* kr = (const ulonglong2*)(myK + ii*DD);
            u64t s0 = 0ull, s1 = 0ull, s2 = 0ull, s3 = 0ull;
            #pragma unroll
            for (int jj = 0; jj < 4; jj++) {
                ulonglong2 ka = kr[2*jj];
                fma2(s0, Qp[4*jj+0], ka.x);
                fma2(s1, Qp[4*jj+1], ka.y);
                ulonglong2 kb = kr[2*jj+1];
                fma2(s2, Qp[4*jj+2], kb.x);
                fma2(s3, Qp[4*jj+3], kb.y);
            }
            svals[ii] = hadd2(add2(add2(s0, s1), add2(s2, s3)));
        }

        // ---- phase 2: ACHK independent decay+exp ----
        const float du0 = (float)(q - ibase);
        #pragma unroll
        for (int ii = 0; ii < ACHK; ii++) {
            float pd  = (du0 - (float)ii) * (Ppq - myP[ii]) * ((Et - myE[ii]) * invEt);
            float dec = __expf(negtheta * pd);
            svals[ii] = __expf(svals[ii] * (SCALE * dec));
        }

        // ---- phase 3: rank-ACHK accumulation (masked) ----
        #pragma unroll
        for (int ii = 0; ii < ACHK; ii++) {
            float p = (ii < iend) ? svals[ii] : 0.0f;
            l += p;
            u64t pp = pk2(p, p);
            const ulonglong2* vr = (const ulonglong2*)(myV + ii*DD);
            #pragma unroll
            for (int jj = 0; jj < 8; jj++) {
                ulonglong2 vv = vr[jj];
                fma2(ctxp[2*jj],   pp, vv.x);
                fma2(ctxp[2*jj+1], pp, vv.y);
            }
        }
        buf ^= 1;
    }
    cpa_wait0();                              // drain dangling prefetch

    // ---- combine: plain sums across the 8 splits (alias SB as [7][AQ][33]) ----
    __syncthreads();
    if (sp != 0) {
        float* dst = SB + ((sp - 1)*AQ + ql)*33;
        dst[0] = l;
        #pragma unroll
        for (int p = 0; p < 16; p++) unpk2(ctxp[p], dst[1 + 2*p], dst[2 + 2*p]);
    }
    __syncthreads();
    if (sp == 0 && active) {
        float ctx[DD];
        #pragma unroll
        for (int p = 0; p < 16; p++) unpk2(ctxp[p], ctx[2*p], ctx[2*p+1]);
        #pragma unroll
        for (int s2 = 0; s2 < NSP-1; s2++) {
            const float* src = SB + (s2*AQ + ql)*33;
            l += src[0];
            #pragma unroll
            for (int d = 0; d < DD; d++) ctx[d] += src[1+d];
        }
        float inv = 1.0f / l;
        float* op = &g_ctx[((long)(b*(SS-1) + (q-1)))*EMB + h*DD];
        #pragma unroll
        for (int d = 0; d < DD; d++) op[d] = ctx[d] * inv;
    }
}

// =====================================================================
// Kernel 4: feat=[ctx, e_{t+1}] (256) -> relu(W1)+b1 (128) -> W2 -> sigmoid
// 8 tokens/block (512 blocks), 512 threads = (col j, k-quarter).
// =====================================================================
__global__ void __launch_bounds__(512) mlp_kernel(
    const float* __restrict__ W1, const float* __restrict__ b1,
    const float* __restrict__ W2, const float* __restrict__ b2,
    float* __restrict__ out, int out_size)
{
    __shared__ float feat[TOK][2*EMB];
    __shared__ float pbuf[3][TOK][EMB];
    __shared__ float h1s[TOK][EMB + 4];

    const int tid = threadIdx.x;
    const int j   = tid & 127;
    const int qt  = tid >> 7;            // quarter 0..3
    const int base = blockIdx.x * TOK;
    const int ntok = min(TOK, NQ - base);

    if (qt == 0) {
        #pragma unroll
        for (int t = 0; t < TOK; t++) {
            int n = base + t; if (n >= NQ) n = NQ - 1;
            feat[t][j] = g_ctx[(long)n*EMB + j];
        }
    } else if (qt == 1) {
        #pragma unroll
        for (int t = 0; t < TOK; t++) {
            int n = base + t; if (n >= NQ) n = NQ - 1;
            int bb = n / (SS-1), tq = n % (SS-1);
            feat[t][EMB + j] = g_e[(bb*SS + tq + 1)*EMB + j];
        }
    }
    __syncthreads();

    const int koff = qt * 64;            // quarter of W1's 256 rows
    u64t accp[TOK];
    #pragma unroll
    for (int t = 0; t < TOK; t++) accp[t] = 0ull;
    #pragma unroll 4
    for (int kk = 0; kk < 64; kk += 4) {
        int k = koff + kk;
        float w0 = W1[(k+0)*EMB + j], w1 = W1[(k+1)*EMB + j];
        float w2 = W1[(k+2)*EMB + j], w3 = W1[(k+3)*EMB + j];
        u64t wA = pk2(w0, w1), wB = pk2(w2, w3);
        #pragma unroll
        for (int t = 0; t < TOK; t++) {
            ulonglong2 f = *(const ulonglong2*)&feat[t][k];
            fma2(accp[t], f.x, wA);
            fma2(accp[t], f.y, wB);
        }
    }
    if (qt) {
        #pragma unroll
        for (int t = 0; t < TOK; t++) pbuf[qt-1][t][j] = hadd2(accp[t]);
    }
    __syncthreads();
    if (!qt) {
        float bbv = b1[j];
        #pragma unroll
        for (int t = 0; t < TOK; t++)
            h1s[t][j] = fmaxf(hadd2(accp[t]) + pbuf[0][t][j] + pbuf[1][t][j]
                              + pbuf[2][t][j] + bbv, 0.f);
    }
    __syncthreads();

    // W2 dot: warp per token (16 warps; first 8 used), shfl reduce
    const int wid = tid >> 5, lane = tid & 31;
    if (wid < ntok) {
        float4 w2v = ((const float4*)W2)[lane];
        float4 hv = *(const float4*)&h1s[wid][lane*4];
        float s = hv.x*w2v.x + hv.y*w2v.y + hv.z*w2v.z + hv.w*w2v.w;
        #pragma unroll
        for (int o = 16; o; o >>= 1) s += __shfl_xor_sync(0xffffffffu, s, o);
        if (lane == 0) {
            float logit = s + b2[0];
            float pred = 1.0f / (1.0f + __expf(-logit));
            int n = base + wid;
            out[n] = pred;
            if (out_size >= 2*NQ) out[NQ + n] = 1.0f;  // valid = True
        }
    }
}

// =====================================================================
extern "C" void kernel_launch(void* const* d_in, const int* in_sizes, int n_in,
                              void* d_out, int out_size)
{
    const int*   idxs = (const int*)  d_in[0];
    const int*   flgs = (const int*)  d_in[1];
    const float* gaps = (const float*)d_in[2];
    const float* item = (const float*)d_in[3];
    const float* ansE = (const float*)d_in[4];
    const float* Wq = (const float*)d_in[5];  const float* bq = (const float*)d_in[6];
    const float* Wk = (const float*)d_in[7];  const float* bk = (const float*)d_in[8];
    const float* Wv = (const float*)d_in[9];  const float* bv = (const float*)d_in[10];
    const float* Wh = (const float*)d_in[11]; const float* bh = (const float*)d_in[12];
    const float* W1 = (const float*)d_in[13]; const float* b1 = (const float*)d_in[14];
    const float* W2 = (const float*)d_in[15]; const float* b2 = (const float*)d_in[16];
    const float* th = (const float*)d_in[17];

    prep_kernel<<<NTOK/TOK, 512>>>(idxs, flgs, item, ansE,
                                   Wq, bq, Wk, bk, Wv, bv, Wh, bh);
    scan_kernel<<<dim3(BB, HH+1), 1024>>>(gaps, th);
    attn_kernel<<<dim3(AQ, BB*HH), 256>>>();
    mlp_kernel<<<(NQ + TOK - 1)/TOK, 512>>>(W1, b1, W2, b2, (float*)d_out, out_size);
}

// round 14
// speedup vs baseline: 1.2704x; 1.2704x over previous
#include <cuda_runtime.h>
#include <cuda_bf16.h>
#include <cstdint>
#include <math.h>

// Problem constants
#define BB   4
#define SS   1024
#define EMB  128
#define HH   4
#define DD   32
#define NTOK (BB*SS)          // 4096
#define NQ   (BB*(SS-1))      // 4092
#define SCALE 0.17677669529663687f  // 1/sqrt(32)
#define TOK  16               // tokens per block (prep / mlp)
#define ACHK 8                // attention staging chunk rows
#define AQ   32               // attention queries per tile
#define NSP  8                // attention splits (warps) per block

typedef unsigned long long u64t;
typedef unsigned int       u32t;

// ---------------- packed f32x2 helpers (SASS FFMA2 path) ---------------------
__device__ __forceinline__ u64t pk2(float lo, float hi){
    u64t r; asm("mov.b64 %0,{%1,%2};":"=l"(r):"f"(lo),"f"(hi)); return r;
}
__device__ __forceinline__ void fma2(u64t& d, u64t a, u64t b){
    asm("fma.rn.f32x2 %0,%1,%2,%0;":"+l"(d):"l"(a),"l"(b));
}
__device__ __forceinline__ u64t add2(u64t a, u64t b){
    u64t r; asm("add.rn.f32x2 %0,%1,%2;":"=l"(r):"l"(a),"l"(b)); return r;
}
__device__ __forceinline__ void unpk2(u64t v, float& lo, float& hi){
    asm("mov.b64 {%0,%1},%2;":"=f"(lo),"=f"(hi):"l"(v));
}
__device__ __forceinline__ float hadd2(u64t v){
    float lo, hi; unpk2(v, lo, hi); return lo + hi;
}

// ---------------- cp.async helpers ------------------------------------------
__device__ __forceinline__ void cpa16(u32t s, const void* g){
    asm volatile("cp.async.ca.shared.global [%0], [%1], 16;" :: "r"(s), "l"(g));
}
__device__ __forceinline__ void cpa4(u32t s, const void* g){
    asm volatile("cp.async.ca.shared.global [%0], [%1], 4;" :: "r"(s), "l"(g));
}
__device__ __forceinline__ void cpa_commit(){
    asm volatile("cp.async.commit_group;");
}
__device__ __forceinline__ void cpa_wait1(){
    asm volatile("cp.async.wait_group 1;");
}
__device__ __forceinline__ void cpa_wait0(){
    asm volatile("cp.async.wait_group 0;");
}

// ---------------- scratch (static device globals; no allocation) -------------
__device__ float g_e  [NTOK*EMB];
__device__ float g_Q  [NTOK*EMB];
__device__ float g_K  [NTOK*EMB];
__device__ float g_V  [NTOK*EMB];
__device__ float g_sr [HH*BB*SS];     // raw Q.K dot per (h,b,s), unscaled
__device__ float g_ctx[NQ*EMB];
__device__ float g_Ep [BB*(SS+1)*HH];
__device__ float g_Pp [BB*(SS+1)];
__device__ float g_theta[HH];

// =====================================================================
// Kernel 1: gather e,a; Q=eWq+bq, K=eWk+bk, inter=[e,a]Wh+bh, V=inter Wv+bv
// + per-token Q.K head dots (half-0: warp w == head w).
// 16 tokens/block (256 blocks), 256 threads = (col j, k-half).
// =====================================================================
__device__ __forceinline__ void pass_acc(const float (*src)[EMB],
                                         const float* __restrict__ Wr0,
                                         int j, int ks0, int cnt, u64t* accp)
{
    #pragma unroll 4
    for (int kk = 0; kk < cnt; kk += 4) {
        float w0 = Wr0[(kk+0)*EMB + j], w1 = Wr0[(kk+1)*EMB + j];
        float w2 = Wr0[(kk+2)*EMB + j], w3 = Wr0[(kk+3)*EMB + j];
        u64t wA = pk2(w0, w1), wB = pk2(w2, w3);
        #pragma unroll
        for (int t = 0; t < TOK; t++) {
            ulonglong2 f = *(const ulonglong2*)&src[t][ks0 + kk];
            fma2(accp[t], f.x, wA);
            fma2(accp[t], f.y, wB);
        }
    }
}

__global__ void __launch_bounds__(256) prep_kernel(
    const int* __restrict__ idxs, const int* __restrict__ flags,
    const float* __restrict__ item_emb, const float* __restrict__ ans_emb,
    const float* __restrict__ Wq, const float* __restrict__ bq,
    const float* __restrict__ Wk, const float* __restrict__ bk,
    const float* __restrict__ Wv, const float* __restrict__ bv,
    const float* __restrict__ Wh, const float* __restrict__ bh)
{
    __shared__ float e_sh[TOK][EMB];
    __shared__ float a_sh[TOK][EMB];
    __shared__ float i_sh[TOK][EMB];
    __shared__ float pbuf[TOK][EMB];

    const int tid  = threadIdx.x;
    const int j    = tid & 127;
    const int half = tid >> 7;           // 0 or 1
    const int koff = half * 64;
    const int base = blockIdx.x * TOK;

    if (half == 0) {
        #pragma unroll
        for (int t = 0; t < TOK; t++)
            e_sh[t][j] = item_emb[(long)idxs[base + t] * EMB + j];
    } else {
        #pragma unroll
        for (int t = 0; t < TOK; t++)
            a_sh[t][j] = ans_emb[flags[base + t] * EMB + j];
    }
    __syncthreads();
    if (half == 0) {
        #pragma unroll
        for (int t = 0; t < TOK; t++)
            g_e[(base + t) * EMB + j] = e_sh[t][j];
    }

    u64t accp[TOK];
    float qv[TOK];                        // final Q values (half-0 only)

    // ---- Q ----
    #pragma unroll
    for (int t = 0; t < TOK; t++) accp[t] = 0ull;
    pass_acc(e_sh, Wq + koff*EMB, j, koff, 64, accp);
    if (half) {
        #pragma unroll
        for (int t = 0; t < TOK; t++) pbuf[t][j] = hadd2(accp[t]);
    }
    __syncthreads();
    if (!half) {
        float bbv = bq[j];
        #pragma unroll
        for (int t = 0; t < TOK; t++) {
            float v = hadd2(accp[t]) + pbuf[t][j] + bbv;
            g_Q[(base+t)*EMB + j] = v;
            qv[t] = v;
        }
    }
    __syncthreads();

    // ---- K (+ fused Q.K head dot) ----
    #pragma unroll
    for (int t = 0; t < TOK; t++) accp[t] = 0ull;
    pass_acc(e_sh, Wk + koff*EMB, j, koff, 64, accp);
    if (half) {
        #pragma unroll
        for (int t = 0; t < TOK; t++) pbuf[t][j] = hadd2(accp[t]);
    }
    __syncthreads();
    if (!half) {
        float bbv = bk[j];
        const int w  = j >> 5;            // warp index == head index (half 0)
        const int bb = base >> 10;        // batch (16 | 1024: block spans one b)
        const int s0 = base & 1023;
        #pragma unroll
        for (int t = 0; t < TOK; t++) {
            float v = hadd2(accp[t]) + pbuf[t][j] + bbv;
            g_K[(base+t)*EMB + j] = v;
            float pr = qv[t] * v;
            #pragma unroll
            for (int o = 16; o; o >>= 1) pr += __shfl_xor_sync(0xffffffffu, pr, o);
            if ((j & 31) == 0) g_sr[(w*BB + bb)*SS + s0 + t] = pr;
        }
    }
    __syncthreads();

    // ---- inter = [e,a] @ Wh + bh ----
    #pragma unroll
    for (int t = 0; t < TOK; t++) accp[t] = 0ull;
    if (!half) pass_acc(e_sh, Wh,           j, 0, 128, accp);
    else       pass_acc(a_sh, Wh + EMB*EMB, j, 0, 128, accp);
    if (half) {
        #pragma unroll
        for (int t = 0; t < TOK; t++) pbuf[t][j] = hadd2(accp[t]);
    }
    __syncthreads();
    if (!half) {
        float bbv = bh[j];
        #pragma unroll
        for (int t = 0; t < TOK; t++)
            i_sh[t][j] = hadd2(accp[t]) + pbuf[t][j] + bbv;
    }
    __syncthreads();

    // ---- V = inter @ Wv + bv ----
    #pragma unroll
    for (int t = 0; t < TOK; t++) accp[t] = 0ull;
    pass_acc(i_sh, Wv + koff*EMB, j, koff, 64, accp);
    if (half) {
        #pragma unroll
        for (int t = 0; t < TOK; t++) pbuf[t][j] = hadd2(accp[t]);
    }
    __syncthreads();
    if (!half) {
        float bbv = bv[j];
        #pragma unroll
        for (int t = 0; t < TOK; t++)
            g_V[(base+t)*EMB + j] = hadd2(accp[t]) + pbuf[t][j] + bbv;
    }
}

// =====================================================================
// Kernel 2: scans (slim). grid (BB, HH+1) x 1024 threads.
// =====================================================================
__device__ __forceinline__ float blk_scan(float v, float* sbuf)
{
    const int lane = threadIdx.x & 31, wid = threadIdx.x >> 5;
    #pragma unroll
    for (int o = 1; o < 32; o <<= 1) {
        float n = __shfl_up_sync(0xffffffffu, v, o);
        if (lane >= o) v += n;
    }
    if (lane == 31) sbuf[wid] = v;
    __syncthreads();
    if (wid == 0) {
        float w = sbuf[lane];
        #pragma unroll
        for (int o = 1; o < 32; o <<= 1) {
            float n = __shfl_up_sync(0xffffffffu, w, o);
            if (lane >= o) w += n;
        }
        sbuf[lane] = w;
    }
    __syncthreads();
    float r = v + (wid ? sbuf[wid - 1] : 0.0f);
    __syncthreads();
    return r;
}

__device__ __forceinline__ float blk_max(float v, float* sbuf)
{
    const int lane = threadIdx.x & 31, wid = threadIdx.x >> 5;
    #pragma unroll
    for (int o = 16; o; o >>= 1) v = fmaxf(v, __shfl_xor_sync(0xffffffffu, v, o));
    if (lane == 0) sbuf[wid] = v;
    __syncthreads();
    if (wid == 0) {
        float w = sbuf[lane];
        #pragma unroll
        for (int o = 16; o; o >>= 1) w = fmaxf(w, __shfl_xor_sync(0xffffffffu, w, o));
        if (lane == 0) sbuf[0] = w;
    }
    __syncthreads();
    float r = sbuf[0];
    __syncthreads();
    return r;
}

__global__ void __launch_bounds__(1024) scan_kernel(
    const float* __restrict__ gaps, const float* __restrict__ theta_raw)
{
    __shared__ float sbuf[32];
    const int b = blockIdx.x;
    const int h = blockIdx.y;
    const int s = threadIdx.x;

    if (h == HH) {
        if (b == 0 && s < HH) {
            float x = theta_raw[s];
            float sp = (x > 20.f) ? x : log1pf(expf(x));
            g_theta[s] = sp + 1e-4f;
        }
        float g = fmaxf(gaps[b*SS + s], 1.0f);
        float gi = blk_scan(g, sbuf);
        g_Pp[b*(SS+1) + s + 1] = gi;
        if (s == 0) g_Pp[b*(SS+1)] = 0.f;
        return;
    }

    float sr = g_sr[(h*BB + b)*SS + s] * SCALE;
    float m = blk_max(sr, sbuf);
    float ex = expf(sr - m);
    float ei = blk_scan(ex, sbuf);
    g_Ep[(b*(SS+1) + s + 1)*HH + h] = ei;
    if (s == 0) g_Ep[(b*(SS+1))*HH + h] = 0.f;
}

// =====================================================================
// Kernel 3: causal decayed attention (exact R12 version).
// grid (32 qtiles heavy-first, 16 bh); block 256 = 32 queries x 8 splits.
// Each split = ONE WARP with private double-buffered cp.async staging.
// =====================================================================
__global__ void __launch_bounds__(256) attn_kernel()
{
    // smem layout (floats):
    //   Ks : [8 split][2 buf][ACHK*DD]   at 0     (4096)
    //   Vs : same                        at 4096  (4096)
    //   Eps: [8][2][ACHK]                at 8192  (128)
    //   Pps: [8][2][ACHK]                at 8320  (128)
    // combine phase aliases [7][AQ][33] (7392) at offset 0 after full drain.
    __shared__ float SB[8448];

    const int qtile = 31 - (int)blockIdx.x;   // heaviest tile first
    const int bh = blockIdx.y;
    const int b = bh >> 2, h = bh & 3;
    const int tid = threadIdx.x;
    const int ql = tid & 31;
    const int sp = tid >> 5;                  // split (= warp) 0..7

    const int q = 1 + qtile*AQ + ql;          // 1..1024
    const bool active = (q <= SS - 1);
    const int qc = active ? q : (SS - 1);

    const float negtheta = -g_theta[h];

    u64t Qp[16];
    {
        const ulonglong2* qp = (const ulonglong2*)&g_Q[(b*SS + qc)*EMB + h*DD];
        #pragma unroll
        for (int jj = 0; jj < 8; jj++) { ulonglong2 v = qp[jj]; Qp[2*jj] = v.x; Qp[2*jj+1] = v.y; }
    }
    const float Et    = g_Ep[(b*(SS+1) + qc)*HH + h];
    const float Ppq   = g_Pp[b*(SS+1) + qc];
    const float invEt = 1.0f / Et;

    float l = 0.f;
    u64t ctxp[16];
    #pragma unroll
    for (int p = 0; p < 16; p++) ctxp[p] = 0ull;

    const u32t sb0 = (u32t)__cvta_generic_to_shared(SB);
    const int nch = (qtile + 1) * (AQ / ACHK);  // ACHK-row chunks covering keys < qmax

    // issue cp.async loads for chunk `c` into buffer `bf` of this warp-split
    auto load_chunk = [&](int c, int bf) {
        int ib = c * ACHK;
        if (ib > SS - ACHK) ib = SS - ACHK;   // clamp (dummy prefetch)
        u32t sK = sb0 + (u32t)((sp*2 + bf) * (ACHK*DD)) * 4u;
        u32t sV = sK + 4096u * 4u;
        // 64 float4 per array; warp lane ql covers f = ql + {0,32}
        #pragma unroll
        for (int rep = 0; rep < 2; rep++) {
            int f = ql + rep*32;
            int r = f >> 3, d4 = f & 7;
            cpa16(sK + (u32t)f*16u, &g_K[(b*SS + ib + r)*EMB + h*DD + d4*4]);
            cpa16(sV + (u32t)f*16u, &g_V[(b*SS + ib + r)*EMB + h*DD + d4*4]);
        }
        if (ql < ACHK) {
            cpa4(sb0 + (u32t)(8192 + (sp*2 + bf)*ACHK + ql) * 4u,
                 &g_Ep[(b*(SS+1) + ib + ql)*HH + h]);
        } else if (ql < 2*ACHK) {
            int r = ql - ACHK;
            cpa4(sb0 + (u32t)(8320 + (sp*2 + bf)*ACHK + r) * 4u,
                 &g_Pp[b*(SS+1) + ib + r]);
        }
        cpa_commit();
    };

    // prologue: chunk sp -> buffer 0
    load_chunk(sp, 0);

    int buf = 0;
    for (int c = sp; c < nch; c += NSP) {
        load_chunk(c + NSP, buf ^ 1);         // prefetch next
        cpa_wait1();                          // this lane's chunk-c group done
        __syncwarp();                         // all lanes' writes visible

        const int ibase = c * ACHK;
        const float* myK = SB        + (sp*2 + buf)*(ACHK*DD);
        const float* myV = SB + 4096 + (sp*2 + buf)*(ACHK*DD);
        const float* myE = SB + 8192 + (sp*2 + buf)*ACHK;
        const float* myP = SB + 8320 + (sp*2 + buf)*ACHK;

        int iend = q - ibase;
        if (iend > ACHK) iend = ACHK;
        if (!active) iend = 0;

        // ---- phase 1: ACHK independent dot products ----
        float svals[ACHK];
        #pragma unroll
        for (int ii = 0; ii < ACHK; ii++) {
            const ulonglong2* kr = (const ulonglong2*)(myK + ii*DD);
            u64t s0 = 0ull, s1 = 0ull, s2 = 0ull, s3 = 0ull;
            #pragma unroll
            for (int jj = 0; jj < 4; jj++) {
                ulonglong2 ka = kr[2*jj];
                fma2(s0, Qp[4*jj+0], ka.x);
                fma2(s1, Qp[4*jj+1], ka.y);
                ulonglong2 kb = kr[2*jj+1];
                fma2(s2, Qp[4*jj+2], kb.x);
                fma2(s3, Qp[4*jj+3], kb.y);
            }
            svals[ii] = hadd2(add2(add2(s0, s1), add2(s2, s3)));
        }

        // ---- phase 2: ACHK independent decay+exp ----
        const float du0 = (float)(q - ibase);
        #pragma unroll
        for (int ii = 0; ii < ACHK; ii++) {
            float pd  = (du0 - (float)ii) * (Ppq - myP[ii]) * ((Et - myE[ii]) * invEt);
            float dec = __expf(negtheta * pd);
            svals[ii] = __expf(svals[ii] * (SCALE * dec));
        }

        // ---- phase 3: rank-ACHK accumulation (masked) ----
        #pragma unroll
        for (int ii = 0; ii < ACHK; ii++) {
            float p = (ii < iend) ? svals[ii] : 0.0f;
            l += p;
            u64t pp = pk2(p, p);
            const ulonglong2* vr = (const ulonglong2*)(myV + ii*DD);
            #pragma unroll
            for (int jj = 0; jj < 8; jj++) {
                ulonglong2 vv = vr[jj];
                fma2(ctxp[2*jj],   pp, vv.x);
                fma2(ctxp[2*jj+1], pp, vv.y);
            }
        }
        buf ^= 1;
    }
    cpa_wait0();                              // drain dangling prefetch

    // ---- combine: plain sums across the 8 splits (alias SB as [7][AQ][33]) ----
    __syncthreads();
    if (sp != 0) {
        float* dst = SB + ((sp - 1)*AQ + ql)*33;
        dst[0] = l;
        #pragma unroll
        for (int p = 0; p < 16; p++) unpk2(ctxp[p], dst[1 + 2*p], dst[2 + 2*p]);
    }
    __syncthreads();
    if (sp == 0 && active) {
        float ctx[DD];
        #pragma unroll
        for (int p = 0; p < 16; p++) unpk2(ctxp[p], ctx[2*p], ctx[2*p+1]);
        #pragma unroll
        for (int s2 = 0; s2 < NSP-1; s2++) {
            const float* src = SB + (s2*AQ + ql)*33;
            l += src[0];
            #pragma unroll
            for (int d = 0; d < DD; d++) ctx[d] += src[1+d];
        }
        float inv = 1.0f / l;
        float* op = &g_ctx[((long)(b*(SS-1) + (q-1)))*EMB + h*DD];
        #pragma unroll
        for (int d = 0; d < DD; d++) op[d] = ctx[d] * inv;
    }
}

// =====================================================================
// Kernel 4: feat=[ctx, e_{t+1}] (256) -> relu(W1)+b1 (128) -> W2 -> sigmoid
// 16 tokens/block (256 blocks), 256 threads = (col j, k-half).
// =====================================================================
__global__ void __launch_bounds__(256) mlp_kernel(
    const float* __restrict__ W1, const float* __restrict__ b1,
    const float* __restrict__ W2, const float* __restrict__ b2,
    float* __restrict__ out, int out_size)
{
    __shared__ float feat[TOK][2*EMB];
    __shared__ float pbuf[TOK][EMB];
    __shared__ float h1s[TOK][EMB + 4];

    const int tid  = threadIdx.x;
    const int j    = tid & 127;
    const int half = tid >> 7;
    const int base = blockIdx.x * TOK;
    const int ntok = min(TOK, NQ - base);

    #pragma unroll
    for (int t = 0; t < TOK; t++) {
        int n = base + t; if (n >= NQ) n = NQ - 1;
        if (half == 0) {
            feat[t][j] = g_ctx[(long)n*EMB + j];
        } else {
            int bb = n / (SS-1), tq = n % (SS-1);
            feat[t][EMB + j] = g_e[(bb*SS + tq + 1)*EMB + j];
        }
    }
    __syncthreads();

    const int koff = half * EMB;
    u64t accp[TOK];
    #pragma unroll
    for (int t = 0; t < TOK; t++) accp[t] = 0ull;
    #pragma unroll 4
    for (int kk = 0; kk < EMB; kk += 4) {
        int k = koff + kk;
        float w0 = W1[(k+0)*EMB + j], w1 = W1[(k+1)*EMB + j];
        float w2 = W1[(k+2)*EMB + j], w3 = W1[(k+3)*EMB + j];
        u64t wA = pk2(w0, w1), wB = pk2(w2, w3);
        #pragma unroll
        for (int t = 0; t < TOK; t++) {
            ulonglong2 f = *(const ulonglong2*)&feat[t][k];
            fma2(accp[t], f.x, wA);
            fma2(accp[t], f.y, wB);
        }
    }
    if (half) {
        #pragma unroll
        for (int t = 0; t < TOK; t++) pbuf[t][j] = hadd2(accp[t]);
    }
    __syncthreads();
    if (!half) {
        float bbv = b1[j];
        #pragma unroll
        for (int t = 0; t < TOK; t++)
            h1s[t][j] = fmaxf(hadd2(accp[t]) + pbuf[t][j] + bbv, 0.f);
    }
    __syncthreads();

    // W2 dot: warp per token (8 warps x 2 tokens), shfl reduce
    const int wid = tid >> 5, lane = tid & 31;
    float4 w2v = ((const float4*)W2)[lane];
    for (int t = wid; t < ntok; t += 8) {
        float4 hv = *(const float4*)&h1s[t][lane*4];
        float s = hv.x*w2v.x + hv.y*w2v.y + hv.z*w2v.z + hv.w*w2v.w;
        #pragma unroll
        for (int o = 16; o; o >>= 1) s += __shfl_xor_sync(0xffffffffu, s, o);
        if (lane == 0) {
            float logit = s + b2[0];
            float pred = 1.0f / (1.0f + __expf(-logit));
            int n = base + t;
            out[n] = pred;
            if (out_size >= 2*NQ) out[NQ + n] = 1.0f;  // valid = True
        }
    }
}

// =====================================================================
extern "C" void kernel_launch(void* const* d_in, const int* in_sizes, int n_in,
                              void* d_out, int out_size)
{
    const int*   idxs = (const int*)  d_in[0];
    const int*   flgs = (const int*)  d_in[1];
    const float* gaps = (const float*)d_in[2];
    const float* item = (const float*)d_in[3];
    const float* ansE = (const float*)d_in[4];
    const float* Wq = (const float*)d_in[5];  const float* bq = (const float*)d_in[6];
    const float* Wk = (const float*)d_in[7];  const float* bk = (const float*)d_in[8];
    const float* Wv = (const float*)d_in[9];  const float* bv = (const float*)d_in[10];
    const float* Wh = (const float*)d_in[11]; const float* bh = (const float*)d_in[12];
    const float* W1 = (const float*)d_in[13]; const float* b1 = (const float*)d_in[14];
    const float* W2 = (const float*)d_in[15]; const float* b2 = (const float*)d_in[16];
    const float* th = (const float*)d_in[17];

    prep_kernel<<<NTOK/TOK, 256>>>(idxs, flgs, item, ansE,
                                   Wq, bq, Wk, bk, Wv, bv, Wh, bh);
    scan_kernel<<<dim3(BB, HH+1), 1024>>>(gaps, th);
    attn_kernel<<<dim3(AQ, BB*HH), 256>>>();
    mlp_kernel<<<(NQ + TOK - 1)/TOK, 256>>>(W1, b1, W2, b2, (float*)d_out, out_size);
}